// round 9
// baseline (speedup 1.0000x reference)
#include <cuda_runtime.h>
#include <cstdint>

// VQ via legacy mma.sync tf32 split GEMM (sm_103-safe).
// R9: TILE_M=256 (32 rows/warp, 2 m16 tiles), merged hl+lh accumulator chain,
// cp.async double-buffered B quarters. 1 CTA/SM, grid 512.

#define D        64
#define K        512
#define TILE_M   256
#define THREADS  256
#define PAD      68

typedef unsigned long long u64;
typedef unsigned int       u32;

// ---------------- device scratch ----------------
__device__ float g_embT[K * D];        // [512][64] codebook rows fp32
__device__ uint4 g_Bfrag[64 * 8 * 32]; // fragment-ordered tf32 B: [c][chunk][lane]
__device__ float g_en2[K];
__device__ float g_err_sum;
__device__ u32   g_done;

__device__ __forceinline__ u32 tf32_rna(float v) {
    u32 r; asm("cvt.rna.tf32.f32 %0, %1;" : "=r"(r) : "f"(v)); return r;
}
__device__ __forceinline__ u32 smem_u32(const void* p) {
    u32 a;
    asm("{ .reg .u64 t; cvta.to.shared.u64 t, %1; cvt.u32.u64 %0, t; }" : "=r"(a) : "l"(p));
    return a;
}

#define MMA_TF32(c0, c1, c2, c3, a0, a1, a2, a3, b0, b1)                     \
    asm volatile("mma.sync.aligned.m16n8k8.row.col.f32.tf32.tf32.f32 "      \
                 "{%0,%1,%2,%3}, {%4,%5,%6,%7}, {%8,%9}, {%0,%1,%2,%3};"    \
                 : "+f"(c0), "+f"(c1), "+f"(c2), "+f"(c3)                   \
                 : "r"(a0), "r"(a1), "r"(a2), "r"(a3), "r"(b0), "r"(b1))

#define CP16(dst, src) \
    asm volatile("cp.async.cg.shared.global [%0], [%1], 16;" :: "r"(dst), "l"(src))
#define CP_COMMIT() asm volatile("cp.async.commit_group;" ::: "memory")
#define CP_WAIT0()  asm volatile("cp.async.wait_group 0;" ::: "memory")

// ---------------- precompute ----------------
__global__ void vq_pre(const float* __restrict__ emb) {
    int gt = blockIdx.x * blockDim.x + threadIdx.x;
    int stride = gridDim.x * blockDim.x;
    if (gt == 0) { g_err_sum = 0.0f; g_done = 0u; }
    for (int i = gt; i < K * D; i += stride) {
        int k = i >> 6, d = i & 63;
        g_embT[i] = emb[d * K + k];
    }
    for (int k = gt; k < K; k += stride) {
        float s = 0.0f;
        for (int d = 0; d < D; d++) {
            float v = emb[d * K + k];
            s = __fadd_rn(s, __fmul_rn(v, v));
        }
        g_en2[k] = s;
    }
    // fragment-ordered B: [c][j][lane]; j<4 hi chunks, j>=4 lo chunks.
    for (int idx = gt; idx < 64 * 8 * 32; idx += stride) {
        int c = idx >> 8;
        int j = (idx >> 5) & 7;
        int l = idx & 31;
        int g = l >> 2, t = l & 3;
        int n = c * 8 + g;
        int jj = j & 3;
        bool lo = (j >= 4);
        u32 w[4];
        #pragma unroll
        for (int p = 0; p < 4; p++) {
            int k = 16 * jj + t + 4 * p;
            float v = emb[k * K + n];
            u32 hib = tf32_rna(v);
            if (!lo) w[p] = hib;
            else     w[p] = tf32_rna(__fsub_rn(v, __uint_as_float(hib)));
        }
        g_Bfrag[idx] = make_uint4(w[0], w[1], w[2], w[3]);
    }
}

// ---------------- smem layout (float indices) ----------------
#define SM_WORK  0                         // max(A 2*256*68 = 34816, B dbl 32768)
#define SM_EN2   34816
#define SM_F     (SM_EN2 + K)              // 35328
#define SM_RED   (SM_F + TILE_M)           // 35584
#define SM_PM    (SM_RED + THREADS)        // 35840 (256 u64 = 512 floats)
#define SMEM_FLOATS (SM_PM + 2 * TILE_M)   // 36352
#define SMEM_SZ  (SMEM_FLOATS * 4)         // 145408 B

__global__ __launch_bounds__(THREADS, 1)
void vq_main(const float* __restrict__ x, float* __restrict__ out,
             int n_x, int loss_idx, int nblocks) {
    extern __shared__ float smem[];
    float* work = smem + SM_WORK;
    float* en2s = smem + SM_EN2;
    float* Fs   = smem + SM_F;
    float* red  = smem + SM_RED;
    u64*   pm   = (u64*)(smem + SM_PM);

    const int tid = threadIdx.x;
    const int wid = tid >> 5, lid = tid & 31;
    const int g = lid >> 2, t = lid & 3;
    const long mbase = (long)blockIdx.x * TILE_M;

    for (int i = tid; i < K; i += THREADS) en2s[i] = g_en2[i];

    // ---- stage A tile (256 rows) into work: padded tf32 hi/lo ----
    float* Ahi = work;
    float* Alo = work + TILE_M * PAD;
    {
        const float4* xg = (const float4*)(x + mbase * D);
        #pragma unroll
        for (int i = tid; i < TILE_M * D / 4; i += THREADS) {
            int row = i >> 4, col4 = (i & 15) * 4;
            float4 v = xg[i];
            u32 h0 = tf32_rna(v.x), h1 = tf32_rna(v.y), h2 = tf32_rna(v.z), h3 = tf32_rna(v.w);
            u32 l0 = tf32_rna(__fsub_rn(v.x, __uint_as_float(h0)));
            u32 l1 = tf32_rna(__fsub_rn(v.y, __uint_as_float(h1)));
            u32 l2 = tf32_rna(__fsub_rn(v.z, __uint_as_float(h2)));
            u32 l3 = tf32_rna(__fsub_rn(v.w, __uint_as_float(h3)));
            int o = row * PAD + col4;
            *(uint4*)(Ahi + o) = make_uint4(h0, h1, h2, h3);
            *(uint4*)(Alo + o) = make_uint4(l0, l1, l2, l3);
        }
    }
    // F for own row (one row per thread, reference sequential order)
    {
        const float4* xr = (const float4*)(x + (mbase + tid) * D);
        float F = 0.0f;
        #pragma unroll
        for (int i = 0; i < D / 4; i++) {
            float4 v = xr[i];
            F = __fadd_rn(F, __fmul_rn(v.x, v.x));
            F = __fadd_rn(F, __fmul_rn(v.y, v.y));
            F = __fadd_rn(F, __fmul_rn(v.z, v.z));
            F = __fadd_rn(F, __fmul_rn(v.w, v.w));
        }
        Fs[tid] = F;
    }
    __syncthreads();

    // ---- A fragments for two m16 tiles (rows wid*32 .. wid*32+31) ----
    const int rbase = wid * 32;
    u32 ah0[8][4], al0[8][4], ah1[8][4], al1[8][4];
    {
        const int r0 = (rbase + g) * PAD,      r1 = (rbase + g + 8) * PAD;
        const int r2 = (rbase + 16 + g) * PAD, r3 = (rbase + 24 + g) * PAD;
        #pragma unroll
        for (int ks = 0; ks < 8; ks++) {
            int c = ks * 8 + t;
            ah0[ks][0] = __float_as_uint(Ahi[r0 + c]);
            ah0[ks][1] = __float_as_uint(Ahi[r1 + c]);
            ah0[ks][2] = __float_as_uint(Ahi[r0 + c + 4]);
            ah0[ks][3] = __float_as_uint(Ahi[r1 + c + 4]);
            al0[ks][0] = __float_as_uint(Alo[r0 + c]);
            al0[ks][1] = __float_as_uint(Alo[r1 + c]);
            al0[ks][2] = __float_as_uint(Alo[r0 + c + 4]);
            al0[ks][3] = __float_as_uint(Alo[r1 + c + 4]);
            ah1[ks][0] = __float_as_uint(Ahi[r2 + c]);
            ah1[ks][1] = __float_as_uint(Ahi[r3 + c]);
            ah1[ks][2] = __float_as_uint(Ahi[r2 + c + 4]);
            ah1[ks][3] = __float_as_uint(Ahi[r3 + c + 4]);
            al1[ks][0] = __float_as_uint(Alo[r2 + c]);
            al1[ks][1] = __float_as_uint(Alo[r3 + c]);
            al1[ks][2] = __float_as_uint(Alo[r2 + c + 4]);
            al1[ks][3] = __float_as_uint(Alo[r3 + c + 4]);
        }
    }
    const float F0 = Fs[rbase + g],      F1 = Fs[rbase + g + 8];
    const float F2 = Fs[rbase + 16 + g], F3 = Fs[rbase + 24 + g];
    __syncthreads();   // A reads done; work region becomes B double-buffer

    uint4* Bbuf = (uint4*)work;            // 2 x 4096 uint4 (2 x 64 KB)
    const u32 sbB = smem_u32(Bbuf);

    // prologue: copy quarter 0 into buf 0
    {
        const uint4* src = g_Bfrag;
        #pragma unroll
        for (int i = tid; i < 4096; i += THREADS)
            CP16(sbB + i * 16, src + i);
        CP_COMMIT();
    }

    u64 pbA = ~0ULL, pbB = ~0ULL, pbC = ~0ULL, pbD = ~0ULL;

    for (int q = 0; q < 4; q++) {
        CP_WAIT0();
        __syncthreads();                   // buf[q&1] full; prior MMA reads done

        if (q < 3) {                       // overlap next copy with this MMA work
            const uint4* src = g_Bfrag + (q + 1) * 4096;
            const u32 dst = sbB + ((q + 1) & 1) * 65536;
            #pragma unroll
            for (int i = tid; i < 4096; i += THREADS)
                CP16(dst + i * 16, src + i);
            CP_COMMIT();
        }

        const uint4* Bs = Bbuf + (q & 1) * 4096;
        for (int cc = 0; cc < 16; cc++) {
            const uint4* bb = Bs + cc * 256 + lid;
            float A00=0,A01=0,A02=0,A03=0, X00=0,X01=0,X02=0,X03=0;  // tile0: hh, hl+lh
            float A10=0,A11=0,A12=0,A13=0, X10=0,X11=0,X12=0,X13=0;  // tile1
            #pragma unroll
            for (int j = 0; j < 4; j++) {
                uint4 bh = bb[j * 32];
                uint4 bl = bb[(j + 4) * 32];
                MMA_TF32(A00,A01,A02,A03, ah0[2*j][0],ah0[2*j][1],ah0[2*j][2],ah0[2*j][3], bh.x, bh.y);
                MMA_TF32(X00,X01,X02,X03, ah0[2*j][0],ah0[2*j][1],ah0[2*j][2],ah0[2*j][3], bl.x, bl.y);
                MMA_TF32(X00,X01,X02,X03, al0[2*j][0],al0[2*j][1],al0[2*j][2],al0[2*j][3], bh.x, bh.y);
                MMA_TF32(A10,A11,A12,A13, ah1[2*j][0],ah1[2*j][1],ah1[2*j][2],ah1[2*j][3], bh.x, bh.y);
                MMA_TF32(X10,X11,X12,X13, ah1[2*j][0],ah1[2*j][1],ah1[2*j][2],ah1[2*j][3], bl.x, bl.y);
                MMA_TF32(X10,X11,X12,X13, al1[2*j][0],al1[2*j][1],al1[2*j][2],al1[2*j][3], bh.x, bh.y);
                MMA_TF32(A00,A01,A02,A03, ah0[2*j+1][0],ah0[2*j+1][1],ah0[2*j+1][2],ah0[2*j+1][3], bh.z, bh.w);
                MMA_TF32(X00,X01,X02,X03, ah0[2*j+1][0],ah0[2*j+1][1],ah0[2*j+1][2],ah0[2*j+1][3], bl.z, bl.w);
                MMA_TF32(X00,X01,X02,X03, al0[2*j+1][0],al0[2*j+1][1],al0[2*j+1][2],al0[2*j+1][3], bh.z, bh.w);
                MMA_TF32(A10,A11,A12,A13, ah1[2*j+1][0],ah1[2*j+1][1],ah1[2*j+1][2],ah1[2*j+1][3], bh.z, bh.w);
                MMA_TF32(X10,X11,X12,X13, ah1[2*j+1][0],ah1[2*j+1][1],ah1[2*j+1][2],ah1[2*j+1][3], bl.z, bl.w);
                MMA_TF32(X10,X11,X12,X13, al1[2*j+1][0],al1[2*j+1][1],al1[2*j+1][2],al1[2*j+1][3], bh.z, bh.w);
            }
            const int cbase = (q * 16 + cc) * 8 + 2 * t;
            float2 e2 = *(float2*)(en2s + cbase);
            float s;
            u64 p;
            s = __fadd_rn(A00, X00);
            p = ((u64)__float_as_uint(fmaf(-2.0f, s, __fadd_rn(F0, e2.x))) << 9) | (u32)cbase;
            if (p < pbA) pbA = p;
            s = __fadd_rn(A01, X01);
            p = ((u64)__float_as_uint(fmaf(-2.0f, s, __fadd_rn(F0, e2.y))) << 9) | (u32)(cbase + 1);
            if (p < pbA) pbA = p;
            s = __fadd_rn(A02, X02);
            p = ((u64)__float_as_uint(fmaf(-2.0f, s, __fadd_rn(F1, e2.x))) << 9) | (u32)cbase;
            if (p < pbB) pbB = p;
            s = __fadd_rn(A03, X03);
            p = ((u64)__float_as_uint(fmaf(-2.0f, s, __fadd_rn(F1, e2.y))) << 9) | (u32)(cbase + 1);
            if (p < pbB) pbB = p;
            s = __fadd_rn(A10, X10);
            p = ((u64)__float_as_uint(fmaf(-2.0f, s, __fadd_rn(F2, e2.x))) << 9) | (u32)cbase;
            if (p < pbC) pbC = p;
            s = __fadd_rn(A11, X11);
            p = ((u64)__float_as_uint(fmaf(-2.0f, s, __fadd_rn(F2, e2.y))) << 9) | (u32)(cbase + 1);
            if (p < pbC) pbC = p;
            s = __fadd_rn(A12, X12);
            p = ((u64)__float_as_uint(fmaf(-2.0f, s, __fadd_rn(F3, e2.x))) << 9) | (u32)cbase;
            if (p < pbD) pbD = p;
            s = __fadd_rn(A13, X13);
            p = ((u64)__float_as_uint(fmaf(-2.0f, s, __fadd_rn(F3, e2.y))) << 9) | (u32)(cbase + 1);
            if (p < pbD) pbD = p;
        }
        __syncthreads();   // MMA reads of buf[q&1] done before q+2 copy reuses it
    }

    // ---- reduce best across the 4 threads of each mma group ----
    #pragma unroll
    for (int off = 1; off < 4; off <<= 1) {
        u64 qa = __shfl_xor_sync(0xffffffffu, pbA, off);
        u64 qb = __shfl_xor_sync(0xffffffffu, pbB, off);
        u64 qc = __shfl_xor_sync(0xffffffffu, pbC, off);
        u64 qd = __shfl_xor_sync(0xffffffffu, pbD, off);
        if (qa < pbA) pbA = qa;
        if (qb < pbB) pbB = qb;
        if (qc < pbC) pbC = qc;
        if (qd < pbD) pbD = qd;
    }
    if (t == 0) {
        pm[rbase + g]      = pbA;
        pm[rbase + g + 8]  = pbB;
        pm[rbase + g + 16] = pbC;
        pm[rbase + g + 24] = pbD;
    }
    __syncthreads();

    // ---- gather winning code row, error, store (one row per thread) ----
    float err = 0.0f;
    {
        int kst = (int)(pm[tid] & 511ULL);
        const float4* qr = (const float4*)(g_embT + kst * D);
        const float4* xr = (const float4*)(x + (mbase + tid) * D);
        float4* og = (float4*)(out + (mbase + tid) * D);
        #pragma unroll
        for (int i = 0; i < D / 4; i++) {
            float4 qv = qr[i], v = xr[i];
            float u0 = v.x - qv.x, u1 = v.y - qv.y, u2 = v.z - qv.z, u3 = v.w - qv.w;
            err = fmaf(u0, u0, err); err = fmaf(u1, u1, err);
            err = fmaf(u2, u2, err); err = fmaf(u3, u3, err);
            og[i] = qv;
        }
    }

    // ---- loss reduce + last-block finalize ----
    red[tid] = err;
    __syncthreads();
    #pragma unroll
    for (int s = THREADS / 2; s > 0; s >>= 1) {
        if (tid < s) red[tid] += red[tid + s];
        __syncthreads();
    }
    if (tid == 0) {
        atomicAdd(&g_err_sum, red[0]);
        __threadfence();
        u32 done = atomicAdd(&g_done, 1u);
        if (done == (u32)(nblocks - 1)) {
            __threadfence();
            out[loss_idx] = 1.25f * g_err_sum / (float)n_x;
        }
    }
}

extern "C" void kernel_launch(void* const* d_in, const int* in_sizes, int n_in,
                              void* d_out, int out_size) {
    const float* x   = (const float*)d_in[0];
    const float* emb = (const float*)d_in[1];
    float* out = (float*)d_out;

    const int n_x  = in_sizes[0];            // 8388608
    const int grid = n_x / D / TILE_M;       // 512

    cudaFuncSetAttribute(vq_main, cudaFuncAttributeMaxDynamicSharedMemorySize, SMEM_SZ);

    vq_pre<<<64, 256>>>(emb);
    vq_main<<<grid, THREADS, SMEM_SZ>>>(x, out, n_x, out_size - 1, grid);
}

// round 10
// speedup vs baseline: 1.1743x; 1.1743x over previous
#include <cuda_runtime.h>
#include <cstdint>

// VQ via legacy mma.sync tf32 split GEMM (sm_103-safe).
// R10: R8 shape (TILE_M=128, 2 CTAs/SM) + merged hl+lh chain (R9-validated)
// + cp.async double-buffered B eighth-chunks in the reused A-staging region.

#define D        64
#define K        512
#define TILE_M   128
#define THREADS  256
#define PAD      68

typedef unsigned long long u64;
typedef unsigned int       u32;

// ---------------- device scratch ----------------
__device__ float g_embT[K * D];        // [512][64] codebook rows fp32
__device__ uint4 g_Bfrag[64 * 8 * 32]; // fragment-ordered tf32 B: [c][chunk][lane]
__device__ float g_en2[K];
__device__ float g_err_sum;
__device__ u32   g_done;

__device__ __forceinline__ u32 tf32_rna(float v) {
    u32 r; asm("cvt.rna.tf32.f32 %0, %1;" : "=r"(r) : "f"(v)); return r;
}
__device__ __forceinline__ u32 smem_u32(const void* p) {
    u32 a;
    asm("{ .reg .u64 t; cvta.to.shared.u64 t, %1; cvt.u32.u64 %0, t; }" : "=r"(a) : "l"(p));
    return a;
}

#define MMA_TF32(c0, c1, c2, c3, a0, a1, a2, a3, b0, b1)                     \
    asm volatile("mma.sync.aligned.m16n8k8.row.col.f32.tf32.tf32.f32 "      \
                 "{%0,%1,%2,%3}, {%4,%5,%6,%7}, {%8,%9}, {%0,%1,%2,%3};"    \
                 : "+f"(c0), "+f"(c1), "+f"(c2), "+f"(c3)                   \
                 : "r"(a0), "r"(a1), "r"(a2), "r"(a3), "r"(b0), "r"(b1))

#define CP16(dst, src) \
    asm volatile("cp.async.cg.shared.global [%0], [%1], 16;" :: "r"(dst), "l"(src))
#define CP_COMMIT() asm volatile("cp.async.commit_group;" ::: "memory")
#define CP_WAIT0()  asm volatile("cp.async.wait_group 0;" ::: "memory")

// ---------------- precompute ----------------
__global__ void vq_pre(const float* __restrict__ emb) {
    int gt = blockIdx.x * blockDim.x + threadIdx.x;
    int stride = gridDim.x * blockDim.x;
    if (gt == 0) { g_err_sum = 0.0f; g_done = 0u; }
    for (int i = gt; i < K * D; i += stride) {
        int k = i >> 6, d = i & 63;
        g_embT[i] = emb[d * K + k];
    }
    for (int k = gt; k < K; k += stride) {
        float s = 0.0f;
        for (int d = 0; d < D; d++) {
            float v = emb[d * K + k];
            s = __fadd_rn(s, __fmul_rn(v, v));
        }
        g_en2[k] = s;
    }
    // fragment-ordered B: [c][j][lane]; j<4 hi chunks, j>=4 lo chunks.
    for (int idx = gt; idx < 64 * 8 * 32; idx += stride) {
        int c = idx >> 8;
        int j = (idx >> 5) & 7;
        int l = idx & 31;
        int g = l >> 2, t = l & 3;
        int n = c * 8 + g;
        int jj = j & 3;
        bool lo = (j >= 4);
        u32 w[4];
        #pragma unroll
        for (int p = 0; p < 4; p++) {
            int k = 16 * jj + t + 4 * p;
            float v = emb[k * K + n];
            u32 hib = tf32_rna(v);
            if (!lo) w[p] = hib;
            else     w[p] = tf32_rna(__fsub_rn(v, __uint_as_float(hib)));
        }
        g_Bfrag[idx] = make_uint4(w[0], w[1], w[2], w[3]);
    }
}

// ---------------- smem layout (float indices) ----------------
#define SM_WORK  0                        // max(A 2*128*68 = 17408, B dbl 16384)
#define SM_EN2   17408
#define SM_F     (SM_EN2 + K)             // 17920
#define SM_RED   (SM_F + TILE_M)          // 18048
#define SM_PM    (SM_RED + THREADS)       // 18304 (128 u64)
#define SMEM_FLOATS (SM_PM + 2 * TILE_M)  // 18560
#define SMEM_SZ  (SMEM_FLOATS * 4)        // 74240 B

__global__ __launch_bounds__(THREADS, 2)
void vq_main(const float* __restrict__ x, float* __restrict__ out,
             int n_x, int loss_idx, int nblocks) {
    extern __shared__ float smem[];
    float* work = smem + SM_WORK;
    float* en2s = smem + SM_EN2;
    float* Fs   = smem + SM_F;
    float* red  = smem + SM_RED;
    u64*   pm   = (u64*)(smem + SM_PM);

    const int tid = threadIdx.x;
    const int wid = tid >> 5, lid = tid & 31;
    const int g = lid >> 2, t = lid & 3;
    const long mbase = (long)blockIdx.x * TILE_M;

    for (int i = tid; i < K; i += THREADS) en2s[i] = g_en2[i];

    // ---- stage A tile into work (padded hi/lo) ----
    float* Ahi = work;
    float* Alo = work + TILE_M * PAD;
    {
        const float4* xg = (const float4*)(x + mbase * D);
        #pragma unroll
        for (int i = tid; i < TILE_M * D / 4; i += THREADS) {
            int row = i >> 4, col4 = (i & 15) * 4;
            float4 v = xg[i];
            u32 h0 = tf32_rna(v.x), h1 = tf32_rna(v.y), h2 = tf32_rna(v.z), h3 = tf32_rna(v.w);
            u32 l0 = tf32_rna(__fsub_rn(v.x, __uint_as_float(h0)));
            u32 l1 = tf32_rna(__fsub_rn(v.y, __uint_as_float(h1)));
            u32 l2 = tf32_rna(__fsub_rn(v.z, __uint_as_float(h2)));
            u32 l3 = tf32_rna(__fsub_rn(v.w, __uint_as_float(h3)));
            int o = row * PAD + col4;
            *(uint4*)(Ahi + o) = make_uint4(h0, h1, h2, h3);
            *(uint4*)(Alo + o) = make_uint4(l0, l1, l2, l3);
        }
    }
    if (tid < TILE_M) {
        const float4* xr = (const float4*)(x + (mbase + tid) * D);
        float F = 0.0f;
        #pragma unroll
        for (int i = 0; i < D / 4; i++) {
            float4 v = xr[i];
            F = __fadd_rn(F, __fmul_rn(v.x, v.x));
            F = __fadd_rn(F, __fmul_rn(v.y, v.y));
            F = __fadd_rn(F, __fmul_rn(v.z, v.z));
            F = __fadd_rn(F, __fmul_rn(v.w, v.w));
        }
        Fs[tid] = F;
    }
    __syncthreads();

    // ---- A fragments to registers (one m16 tile per warp) ----
    const int rbase = wid * 16;
    u32 ah[8][4], al[8][4];
    {
        const int r0 = (rbase + g) * PAD, r1 = (rbase + g + 8) * PAD;
        #pragma unroll
        for (int ks = 0; ks < 8; ks++) {
            int c = ks * 8 + t;
            ah[ks][0] = __float_as_uint(Ahi[r0 + c]);
            ah[ks][1] = __float_as_uint(Ahi[r1 + c]);
            ah[ks][2] = __float_as_uint(Ahi[r0 + c + 4]);
            ah[ks][3] = __float_as_uint(Ahi[r1 + c + 4]);
            al[ks][0] = __float_as_uint(Alo[r0 + c]);
            al[ks][1] = __float_as_uint(Alo[r1 + c]);
            al[ks][2] = __float_as_uint(Alo[r0 + c + 4]);
            al[ks][3] = __float_as_uint(Alo[r1 + c + 4]);
        }
    }
    const float Fg  = Fs[rbase + g];
    const float Fg8 = Fs[rbase + g + 8];
    __syncthreads();   // A reads done; work region becomes B double buffer

    uint4* Bbuf = (uint4*)work;            // 2 x 2048 uint4 (2 x 32 KB)
    const u32 sbB = smem_u32(Bbuf);

    // prologue: chunk 0 (64 codes) -> buf 0
    {
        const uint4* src = g_Bfrag;
        #pragma unroll
        for (int i = tid; i < 2048; i += THREADS)
            CP16(sbB + i * 16, src + i);
        CP_COMMIT();
    }

    u64 pb0 = ~0ULL, pb1 = ~0ULL;

    for (int e = 0; e < 8; e++) {
        CP_WAIT0();
        __syncthreads();        // buf[e&1] full; all warps done with chunk e-1

        if (e < 7) {            // prefetch next chunk into the other buffer
            const uint4* src = g_Bfrag + (e + 1) * 2048;
            const u32 dst = sbB + ((e + 1) & 1) * 32768;
            #pragma unroll
            for (int i = tid; i < 2048; i += THREADS)
                CP16(dst + i * 16, src + i);
            CP_COMMIT();
        }

        const uint4* Bs = Bbuf + (e & 1) * 2048;
        for (int cc = 0; cc < 8; cc++) {
            const uint4* bb = Bs + cc * 256 + lid;
            float A0=0,A1=0,A2=0,A3=0;   // hh chain
            float X0=0,X1=0,X2=0,X3=0;   // merged hl+lh chain
            #pragma unroll
            for (int j = 0; j < 4; j++) {
                uint4 bh = bb[j * 32];
                uint4 bl = bb[(j + 4) * 32];
                MMA_TF32(A0,A1,A2,A3, ah[2*j][0],ah[2*j][1],ah[2*j][2],ah[2*j][3], bh.x, bh.y);
                MMA_TF32(X0,X1,X2,X3, ah[2*j][0],ah[2*j][1],ah[2*j][2],ah[2*j][3], bl.x, bl.y);
                MMA_TF32(X0,X1,X2,X3, al[2*j][0],al[2*j][1],al[2*j][2],al[2*j][3], bh.x, bh.y);
                MMA_TF32(A0,A1,A2,A3, ah[2*j+1][0],ah[2*j+1][1],ah[2*j+1][2],ah[2*j+1][3], bh.z, bh.w);
                MMA_TF32(X0,X1,X2,X3, ah[2*j+1][0],ah[2*j+1][1],ah[2*j+1][2],ah[2*j+1][3], bl.z, bl.w);
                MMA_TF32(X0,X1,X2,X3, al[2*j+1][0],al[2*j+1][1],al[2*j+1][2],al[2*j+1][3], bh.z, bh.w);
            }
            const int cbase = (e * 8 + cc) * 8 + 2 * t;
            float2 e2 = *(float2*)(en2s + cbase);
            float s;
            u64 p;
            s = __fadd_rn(A0, X0);
            p = ((u64)__float_as_uint(fmaf(-2.0f, s, __fadd_rn(Fg,  e2.x))) << 9) | (u32)cbase;
            if (p < pb0) pb0 = p;
            s = __fadd_rn(A1, X1);
            p = ((u64)__float_as_uint(fmaf(-2.0f, s, __fadd_rn(Fg,  e2.y))) << 9) | (u32)(cbase + 1);
            if (p < pb0) pb0 = p;
            s = __fadd_rn(A2, X2);
            p = ((u64)__float_as_uint(fmaf(-2.0f, s, __fadd_rn(Fg8, e2.x))) << 9) | (u32)cbase;
            if (p < pb1) pb1 = p;
            s = __fadd_rn(A3, X3);
            p = ((u64)__float_as_uint(fmaf(-2.0f, s, __fadd_rn(Fg8, e2.y))) << 9) | (u32)(cbase + 1);
            if (p < pb1) pb1 = p;
        }
        // no trailing sync: next iteration's leading sync is the read-done barrier
    }

    // ---- reduce best across the 4 threads of each mma group ----
    #pragma unroll
    for (int off = 1; off < 4; off <<= 1) {
        u64 q0 = __shfl_xor_sync(0xffffffffu, pb0, off);
        u64 q1 = __shfl_xor_sync(0xffffffffu, pb1, off);
        if (q0 < pb0) pb0 = q0;
        if (q1 < pb1) pb1 = q1;
    }
    __syncthreads();           // MMA/LDS phase fully done before pm reuse
    if (t == 0) {
        pm[rbase + g]     = pb0;
        pm[rbase + g + 8] = pb1;
    }
    __syncthreads();

    // ---- gather winning code row, error, store ----
    float err = 0.0f;
    if (tid < TILE_M) {
        int kst = (int)(pm[tid] & 511ULL);
        const float4* qr = (const float4*)(g_embT + kst * D);
        const float4* xr = (const float4*)(x + (mbase + tid) * D);
        float4* og = (float4*)(out + (mbase + tid) * D);
        #pragma unroll
        for (int i = 0; i < D / 4; i++) {
            float4 qv = qr[i], v = xr[i];
            float u0 = v.x - qv.x, u1 = v.y - qv.y, u2 = v.z - qv.z, u3 = v.w - qv.w;
            err = fmaf(u0, u0, err); err = fmaf(u1, u1, err);
            err = fmaf(u2, u2, err); err = fmaf(u3, u3, err);
            og[i] = qv;
        }
    }

    // ---- loss reduce + last-block finalize ----
    red[tid] = err;
    __syncthreads();
    #pragma unroll
    for (int s = THREADS / 2; s > 0; s >>= 1) {
        if (tid < s) red[tid] += red[tid + s];
        __syncthreads();
    }
    if (tid == 0) {
        atomicAdd(&g_err_sum, red[0]);
        __threadfence();
        u32 done = atomicAdd(&g_done, 1u);
        if (done == (u32)(nblocks - 1)) {
            __threadfence();
            out[loss_idx] = 1.25f * g_err_sum / (float)n_x;
        }
    }
}

extern "C" void kernel_launch(void* const* d_in, const int* in_sizes, int n_in,
                              void* d_out, int out_size) {
    const float* x   = (const float*)d_in[0];
    const float* emb = (const float*)d_in[1];
    float* out = (float*)d_out;

    const int n_x  = in_sizes[0];            // 8388608
    const int grid = n_x / D / TILE_M;       // 1024

    cudaFuncSetAttribute(vq_main, cudaFuncAttributeMaxDynamicSharedMemorySize, SMEM_SZ);

    vq_pre<<<64, 256>>>(emb);
    vq_main<<<grid, THREADS, SMEM_SZ>>>(x, out, n_x, out_size - 1, grid);
}